// round 8
// baseline (speedup 1.0000x reference)
#include <cuda_runtime.h>
#include <math.h>

#define BATCH 32
#define SEQ 4096
#define HIDDEN 2048
#define ROUTE_H 256
#define NUM_EXPERTS 64
#define TOP_K 8
#define LN_EPS 1e-5f

#define NSPLIT 16
#define SCHUNK (SEQ / NSPLIT)        // 256 rows per pool block
#define H4 (HIDDEN / 4)              // 512 float4 columns

#define KB 16                        // K-split blocks for GEMV1
#define KCHUNK (HIDDEN / KB)         // 128 hidden cols per GEMV1 block

// Scratch (no cudaMalloc allowed)
__device__ float g_partial[NSPLIT * BATCH * HIDDEN];   // [sp][b][h] = 4 MB
__device__ float g_hpart[KB * BATCH * ROUTE_H];        // [ks][b][j] = 512 KB
__device__ unsigned int g_cnt[BATCH];                  // per-batch election

// ---------------------------------------------------------------------------
// Kernel 1: partial mean-pool. grid = BATCH*NSPLIT = 512 blocks, 512 threads
// (one resident wave). Each thread accumulates one float4 column over its
// 256-row seq slice with __ldcs (evict-first streaming). Blocks 0..263 also
// issue L2 prefetches for W1/W2 so the router kernel hits L2, not DRAM.
// Block 0 resets the election counters (stream-ordered before kernel 2).
// ---------------------------------------------------------------------------
__global__ void __launch_bounds__(512) pool_partial(
    const float* __restrict__ x,
    const float* __restrict__ W1, const float* __restrict__ W2)
{
    int blk = blockIdx.x;
    int b   = blk / NSPLIT;
    int sp  = blk % NSPLIT;
    int c4  = threadIdx.x;  // 0..511

    if (blk == 0 && c4 < BATCH) g_cnt[c4] = 0u;

    // Warm L2 with W1 (2 MB = 131072 float4 = 256 blocks x 512 threads)
    if (blk < 256) {
        const float4* wp = (const float4*)W1 + (size_t)blk * 512 + c4;
        asm volatile("prefetch.global.L2 [%0];" :: "l"(wp));
    } else if (blk < 264) {
        // W2: 64 KB = 4096 float4 = 8 blocks x 512 threads
        const float4* wp = (const float4*)W2 + (size_t)(blk - 256) * 512 + c4;
        asm volatile("prefetch.global.L2 [%0];" :: "l"(wp));
    }

    const float4* base = (const float4*)(x) +
        ((size_t)b * SEQ + (size_t)sp * SCHUNK) * (size_t)H4 + c4;

    float4 acc = make_float4(0.f, 0.f, 0.f, 0.f);
#pragma unroll 8
    for (int s = 0; s < SCHUNK; s++) {
        float4 v = __ldcs(&base[(size_t)s * H4]);
        acc.x += v.x; acc.y += v.y; acc.z += v.z; acc.w += v.w;
    }

    float4* out = (float4*)(g_partial + ((size_t)sp * BATCH + b) * HIDDEN);
    out[c4] = acc;
}

// ---------------------------------------------------------------------------
// Kernel 2: GEMV1 K-split (grid = BATCH*KB = 512 blocks, 256 threads), float4
// weight loads, with the per-batch finale fused in via last-block election.
// Block (b, ks): fold pooled cols [ks*128, ks*128+128), GEMV1 slice via
// 4-way row-group split (thread t: outputs 4*j4..4*j4+3, rows rg::4), then
// the 16th finisher for batch b runs LN + GELU + GEMV2 + top-8 inline.
// All fold orders fixed -> deterministic output.
// ---------------------------------------------------------------------------
__global__ void __launch_bounds__(ROUTE_H) gemv1_finale(
    const float* __restrict__ W1, const float* __restrict__ b1,
    const float* __restrict__ ln_g, const float* __restrict__ ln_b,
    const float* __restrict__ W2, const float* __restrict__ b2,
    float* __restrict__ out)
{
    __shared__ float sh_pool[KCHUNK];
    __shared__ float sh_g[4 * ROUTE_H];     // 4 row-group partials x 256 outputs
    __shared__ unsigned int s_elect;

    int blk = blockIdx.x;
    int b   = blk / KB;
    int ks  = blk % KB;
    int t   = threadIdx.x;           // 0..255
    int i0  = ks * KCHUNK;

    // Fold NSPLIT partials for this block's 128 pooled columns (L2 hits).
    if (t < KCHUNK) {
        float s = 0.f;
#pragma unroll
        for (int sp = 0; sp < NSPLIT; sp++)
            s += g_partial[((size_t)sp * BATCH + b) * HIDDEN + i0 + t];
        sh_pool[t] = s * (1.0f / SEQ);
    }
    __syncthreads();

    // GEMV1 slice: thread t -> output cols [4*j4, 4*j4+4), row group rg.
    {
        int j4 = t & 63;             // 0..63 (float4 column index)
        int rg = t >> 6;             // 0..3
        float4 acc = make_float4(0.f, 0.f, 0.f, 0.f);
        const float4* wbase = (const float4*)W1 + (size_t)i0 * 64 + j4;
#pragma unroll 8
        for (int r = rg; r < KCHUNK; r += 4) {
            float4 w = wbase[(size_t)r * 64];
            float  p = sh_pool[r];
            acc.x += p * w.x; acc.y += p * w.y;
            acc.z += p * w.z; acc.w += p * w.w;
        }
        ((float4*)sh_g)[rg * 64 + j4] = acc;
    }
    __syncthreads();

    // Combine 4 row groups (fixed order) and publish the h-partial slice.
    g_hpart[((size_t)ks * BATCH + b) * ROUTE_H + t] =
        (sh_g[t] + sh_g[ROUTE_H + t]) +
        (sh_g[2 * ROUTE_H + t] + sh_g[3 * ROUTE_H + t]);

    // ---- election: last finishing block of this batch runs the finale ----
    __threadfence();   // publish g_hpart slice before counting
    if (t == 0) {
        unsigned int old = atomicAdd(&g_cnt[b], 1u);
        s_elect = (old == KB - 1) ? 1u : 0u;
    }
    __syncthreads();
    if (!s_elect) return;
    __threadfence();   // acquire: all 16 slices now visible

    // =================== finale for batch b (256 threads) ===================
    __shared__ float sh_h[ROUTE_H];
    __shared__ float sh_w1r[8], sh_w2r[8];
    __shared__ float sh_logits[NUM_EXPERTS];

    int j    = t;
    int lane = t & 31;
    int warp = t >> 5;

    float h = 0.f;
#pragma unroll
    for (int k = 0; k < KB; k++)
        h += g_hpart[((size_t)k * BATCH + b) * ROUTE_H + j];
    h += b1[j];

    // LN reduce via warp shuffles (8 warps)
    float s1 = h, s2 = h * h;
#pragma unroll
    for (int o = 16; o > 0; o >>= 1) {
        s1 += __shfl_xor_sync(0xffffffffu, s1, o);
        s2 += __shfl_xor_sync(0xffffffffu, s2, o);
    }
    if (lane == 0) { sh_w1r[warp] = s1; sh_w2r[warp] = s2; }
    __syncthreads();
    float t1 = sh_w1r[lane & 7], t2 = sh_w2r[lane & 7];
#pragma unroll
    for (int o = 4; o > 0; o >>= 1) {
        t1 += __shfl_xor_sync(0xffffffffu, t1, o);
        t2 += __shfl_xor_sync(0xffffffffu, t2, o);
    }
    t1 = __shfl_sync(0xffffffffu, t1, 0);
    t2 = __shfl_sync(0xffffffffu, t2, 0);

    float mu  = t1 * (1.0f / ROUTE_H);
    float ms  = t2 * (1.0f / ROUTE_H);
    float inv = rsqrtf(ms - mu * mu + LN_EPS);
    h = (h - mu) * inv * ln_g[j] + ln_b[j];
    h = 0.5f * h * (1.0f + erff(h * 0.70710678118654752f));   // exact GELU
    sh_h[j] = h;
    __syncthreads();

    // GEMV2 with float4 weights: thread t -> experts [4*e4, 4*e4+4),
    // row group rg2 (16 groups of 16 rows). sh_g reused for partials.
    {
        int e4  = t & 15;            // 0..15 (float4 expert index)
        int rg2 = t >> 4;            // 0..15
        float4 acc = make_float4(0.f, 0.f, 0.f, 0.f);
        const float4* wbase = (const float4*)W2 + e4;
#pragma unroll 8
        for (int r = rg2; r < ROUTE_H; r += 16) {
            float4 w = wbase[(size_t)r * 16];
            float  p = sh_h[r];
            acc.x += p * w.x; acc.y += p * w.y;
            acc.z += p * w.z; acc.w += p * w.w;
        }
        ((float4*)sh_g)[rg2 * 16 + e4] = acc;
    }
    __syncthreads();
    if (j < NUM_EXPERTS) {
        float a = 0.f;
#pragma unroll
        for (int rg2 = 0; rg2 < 16; rg2++)
            a += sh_g[rg2 * NUM_EXPERTS + j];
        sh_logits[j] = a + b2[j];
        out[(size_t)b * NUM_EXPERTS + j] = 0.0f;   // d_out poisoned; zero first
    }
    __syncthreads();

    // top-8 + softmax + scatter (strict '>' = first-index tie-break, matching
    // jax.lax.top_k)
    if (j == 0) {
        int   idx[TOP_K];
        float val[TOP_K];
        unsigned long long used = 0ull;
        for (int k = 0; k < TOP_K; k++) {
            float best = -INFINITY;
            int bi = 0;
            for (int e = 0; e < NUM_EXPERTS; e++) {
                if (!((used >> e) & 1ull) && sh_logits[e] > best) {
                    best = sh_logits[e]; bi = e;
                }
            }
            used |= (1ull << bi);
            idx[k] = bi;
            val[k] = best;
        }
        float mx = val[0];
        float denom = 0.f;
        float ex[TOP_K];
        for (int k = 0; k < TOP_K; k++) { ex[k] = expf(val[k] - mx); denom += ex[k]; }
        float rden = 1.0f / denom;
        for (int k = 0; k < TOP_K; k++)
            out[(size_t)b * NUM_EXPERTS + idx[k]] = ex[k] * rden;
    }
}

// ---------------------------------------------------------------------------
extern "C" void kernel_launch(void* const* d_in, const int* in_sizes, int n_in,
                              void* d_out, int out_size) {
    const float* hs   = (const float*)d_in[0];
    const float* W1   = (const float*)d_in[1];
    const float* b1   = (const float*)d_in[2];
    const float* ln_g = (const float*)d_in[3];
    const float* ln_b = (const float*)d_in[4];
    const float* W2   = (const float*)d_in[5];
    const float* b2   = (const float*)d_in[6];
    // d_in[7] = top_k (hardcoded 8)

    float* out = (float*)d_out;

    pool_partial<<<BATCH * NSPLIT, 512>>>(hs, W1, W2);
    gemv1_finale<<<BATCH * KB, ROUTE_H>>>(W1, b1, ln_g, ln_b, W2, b2, out);
}

// round 9
// speedup vs baseline: 1.0489x; 1.0489x over previous
#include <cuda_runtime.h>
#include <math.h>

#define BATCH 32
#define SEQ 4096
#define HIDDEN 2048
#define ROUTE_H 256
#define NUM_EXPERTS 64
#define TOP_K 8
#define LN_EPS 1e-5f

#define NSPLIT 16
#define SCHUNK (SEQ / NSPLIT)        // 256 rows per pool block
#define H4 (HIDDEN / 4)              // 512 float4 columns

#define KB 32                        // K-split blocks for GEMV1
#define KCHUNK (HIDDEN / KB)         // 64 hidden cols per GEMV1 block

// Scratch (no cudaMalloc allowed)
__device__ float g_partial[NSPLIT * BATCH * HIDDEN];   // [sp][b][h] = 4 MB
__device__ float g_hpart[KB * BATCH * ROUTE_H];        // [ks][b][j] = 1 MB
__device__ unsigned int g_cnt[BATCH];                  // per-batch election

// ---------------------------------------------------------------------------
// Kernel 1: partial mean-pool. grid = BATCH*NSPLIT = 512 blocks, 512 threads
// (one resident wave). Each thread accumulates one float4 column over its
// 256-row seq slice with __ldcs (evict-first streaming). Block 0 resets the
// election counters (stream-ordered before kernel 2, graph-replay safe).
// ---------------------------------------------------------------------------
__global__ void __launch_bounds__(512) pool_partial(const float* __restrict__ x) {
    int blk = blockIdx.x;
    int b   = blk / NSPLIT;
    int sp  = blk % NSPLIT;
    int c4  = threadIdx.x;  // 0..511

    if (blk == 0 && c4 < BATCH) g_cnt[c4] = 0u;

    const float4* base = (const float4*)(x) +
        ((size_t)b * SEQ + (size_t)sp * SCHUNK) * (size_t)H4 + c4;

    float4 acc = make_float4(0.f, 0.f, 0.f, 0.f);
#pragma unroll 8
    for (int s = 0; s < SCHUNK; s++) {
        float4 v = __ldcs(&base[(size_t)s * H4]);
        acc.x += v.x; acc.y += v.y; acc.z += v.z; acc.w += v.w;
    }

    float4* out = (float4*)(g_partial + ((size_t)sp * BATCH + b) * HIDDEN);
    out[c4] = acc;
}

// ---------------------------------------------------------------------------
// Kernel 2: GEMV1 K-split (grid = BATCH*KB = 1024 blocks, 256 threads; one
// wave at 8 blocks/SM), scalar W1 loads with 8 independent accumulators,
// per-batch finale fused in via last-block election.
// Block (b, ks): fold pooled cols [ks*64, ks*64+64) (4 threads per column,
// depth-4 fold), 64-row GEMV1 slice, then the 32nd finisher for batch b runs
// LN + GELU + GEMV2 + top-8 inline. All fold orders fixed -> deterministic.
// ---------------------------------------------------------------------------
__global__ void __launch_bounds__(ROUTE_H) gemv1_finale(
    const float* __restrict__ W1, const float* __restrict__ b1,
    const float* __restrict__ ln_g, const float* __restrict__ ln_b,
    const float* __restrict__ W2, const float* __restrict__ b2,
    float* __restrict__ out)
{
    __shared__ float sh_fold[4][KCHUNK];
    __shared__ float sh_pool[KCHUNK];
    __shared__ unsigned int s_elect;

    int blk = blockIdx.x;
    int b   = blk / KB;
    int ks  = blk % KB;
    int t   = threadIdx.x;           // 0..255
    int i0  = ks * KCHUNK;

    // Fold NSPLIT=16 partials for 64 columns: thread (col = t&63, part = t>>6)
    // folds 4 partials; combine below. All loads L2-resident (just written).
    {
        int col  = t & (KCHUNK - 1);
        int part = t >> 6;           // 0..3
        float s = 0.f;
#pragma unroll
        for (int q = 0; q < NSPLIT / 4; q++) {
            int sp = part * (NSPLIT / 4) + q;
            s += g_partial[((size_t)sp * BATCH + b) * HIDDEN + i0 + col];
        }
        sh_fold[part][col] = s;
    }
    __syncthreads();
    if (t < KCHUNK) {
        sh_pool[t] = ((sh_fold[0][t] + sh_fold[1][t]) +
                      (sh_fold[2][t] + sh_fold[3][t])) * (1.0f / SEQ);
    }
    __syncthreads();

    // GEMV1 slice: thread t -> output column t, 64 rows, 8 independent
    // accumulators (coalesced W1 reads across t).
    float a0 = 0.f, a1 = 0.f, a2 = 0.f, a3 = 0.f;
    float a4 = 0.f, a5 = 0.f, a6 = 0.f, a7 = 0.f;
#pragma unroll
    for (int r = 0; r < KCHUNK; r += 8) {
        const float* w = W1 + (size_t)(i0 + r) * ROUTE_H + t;
        a0 += sh_pool[r + 0] * w[0 * ROUTE_H];
        a1 += sh_pool[r + 1] * w[1 * ROUTE_H];
        a2 += sh_pool[r + 2] * w[2 * ROUTE_H];
        a3 += sh_pool[r + 3] * w[3 * ROUTE_H];
        a4 += sh_pool[r + 4] * w[4 * ROUTE_H];
        a5 += sh_pool[r + 5] * w[5 * ROUTE_H];
        a6 += sh_pool[r + 6] * w[6 * ROUTE_H];
        a7 += sh_pool[r + 7] * w[7 * ROUTE_H];
    }
    g_hpart[((size_t)ks * BATCH + b) * ROUTE_H + t] =
        ((a0 + a1) + (a2 + a3)) + ((a4 + a5) + (a6 + a7));

    // ---- election: last finishing block of this batch runs the finale ----
    __threadfence();   // publish g_hpart slice before counting
    if (t == 0) {
        unsigned int old = atomicAdd(&g_cnt[b], 1u);
        s_elect = (old == KB - 1) ? 1u : 0u;
    }
    __syncthreads();
    if (!s_elect) return;
    __threadfence();   // acquire: all 32 slices now visible

    // =================== finale for batch b (256 threads) ===================
    __shared__ float sh_h[ROUTE_H];
    __shared__ float sh_w1r[8], sh_w2r[8];
    __shared__ float sh_part[ROUTE_H];
    __shared__ float sh_logits[NUM_EXPERTS];

    int j    = t;
    int lane = t & 31;
    int warp = t >> 5;

    float h = 0.f;
#pragma unroll
    for (int k = 0; k < KB; k++)
        h += g_hpart[((size_t)k * BATCH + b) * ROUTE_H + j];
    h += b1[j];

    // LN reduce via warp shuffles (8 warps)
    float s1 = h, s2 = h * h;
#pragma unroll
    for (int o = 16; o > 0; o >>= 1) {
        s1 += __shfl_xor_sync(0xffffffffu, s1, o);
        s2 += __shfl_xor_sync(0xffffffffu, s2, o);
    }
    if (lane == 0) { sh_w1r[warp] = s1; sh_w2r[warp] = s2; }
    __syncthreads();
    float t1 = sh_w1r[lane & 7], t2 = sh_w2r[lane & 7];
#pragma unroll
    for (int o = 4; o > 0; o >>= 1) {
        t1 += __shfl_xor_sync(0xffffffffu, t1, o);
        t2 += __shfl_xor_sync(0xffffffffu, t2, o);
    }
    t1 = __shfl_sync(0xffffffffu, t1, 0);
    t2 = __shfl_sync(0xffffffffu, t2, 0);

    float mu  = t1 * (1.0f / ROUTE_H);
    float ms  = t2 * (1.0f / ROUTE_H);
    float inv = rsqrtf(ms - mu * mu + LN_EPS);
    h = (h - mu) * inv * ln_g[j] + ln_b[j];
    h = 0.5f * h * (1.0f + erff(h * 0.70710678118654752f));   // exact GELU
    sh_h[j] = h;
    __syncthreads();

    // GEMV2, K-split 4 within the block: 256 threads = 64 experts x 4 slices
    {
        int e   = j & (NUM_EXPERTS - 1);
        int ks2 = j >> 6;
        int r0  = ks2 * (ROUTE_H / 4);
        float a = 0.f;
#pragma unroll 8
        for (int i = 0; i < ROUTE_H / 4; i++)
            a += sh_h[r0 + i] * W2[(size_t)(r0 + i) * NUM_EXPERTS + e];
        sh_part[j] = a;
    }
    __syncthreads();
    if (j < NUM_EXPERTS) {
        sh_logits[j] = ((sh_part[j] + sh_part[j + 64]) +
                        (sh_part[j + 128] + sh_part[j + 192])) + b2[j];
        out[(size_t)b * NUM_EXPERTS + j] = 0.0f;   // d_out poisoned; zero first
    }
    __syncthreads();

    // top-8 + softmax + scatter (strict '>' = first-index tie-break, matching
    // jax.lax.top_k)
    if (j == 0) {
        int   idx[TOP_K];
        float val[TOP_K];
        unsigned long long used = 0ull;
        for (int k = 0; k < TOP_K; k++) {
            float best = -INFINITY;
            int bi = 0;
            for (int e = 0; e < NUM_EXPERTS; e++) {
                if (!((used >> e) & 1ull) && sh_logits[e] > best) {
                    best = sh_logits[e]; bi = e;
                }
            }
            used |= (1ull << bi);
            idx[k] = bi;
            val[k] = best;
        }
        float mx = val[0];
        float denom = 0.f;
        float ex[TOP_K];
        for (int k = 0; k < TOP_K; k++) { ex[k] = expf(val[k] - mx); denom += ex[k]; }
        float rden = 1.0f / denom;
        for (int k = 0; k < TOP_K; k++)
            out[(size_t)b * NUM_EXPERTS + idx[k]] = ex[k] * rden;
    }
}

// ---------------------------------------------------------------------------
extern "C" void kernel_launch(void* const* d_in, const int* in_sizes, int n_in,
                              void* d_out, int out_size) {
    const float* hs   = (const float*)d_in[0];
    const float* W1   = (const float*)d_in[1];
    const float* b1   = (const float*)d_in[2];
    const float* ln_g = (const float*)d_in[3];
    const float* ln_b = (const float*)d_in[4];
    const float* W2   = (const float*)d_in[5];
    const float* b2   = (const float*)d_in[6];
    // d_in[7] = top_k (hardcoded 8)

    float* out = (float*)d_out;

    pool_partial<<<BATCH * NSPLIT, 512>>>(hs);
    gemv1_finale<<<BATCH * KB, ROUTE_H>>>(W1, b1, ln_g, ln_b, W2, b2, out);
}

// round 10
// speedup vs baseline: 1.0627x; 1.0132x over previous
#include <cuda_runtime.h>
#include <math.h>

#define BATCH 32
#define SEQ 4096
#define HIDDEN 2048
#define ROUTE_H 256
#define NUM_EXPERTS 64
#define TOP_K 8
#define LN_EPS 1e-5f

#define NSPLIT 16                    // blocks per batch (also K-split for GEMV1)
#define SCHUNK (SEQ / NSPLIT)        // 256 seq rows per block
#define H4 (HIDDEN / 4)              // 512 float4 columns
#define KCHUNK (HIDDEN / NSPLIT)     // 128 hidden cols per GEMV1 slice
#define NTHR 512

// Scratch (no cudaMalloc allowed). Zero-initialized at module load; counters
// are reset by the finale block each launch -> graph-replay safe.
__device__ float g_partial[NSPLIT * BATCH * HIDDEN];   // [sp][b][h] = 4 MB
__device__ float g_hpart[NSPLIT * BATCH * ROUTE_H];    // [ks][b][j] = 512 KB
__device__ unsigned int g_cnt1[BATCH];                 // pool-done election
__device__ unsigned int g_cnt2[BATCH];                 // gemv-done election

// ---------------------------------------------------------------------------
// ONE fused kernel. grid = BATCH*NSPLIT = 512 blocks x 512 threads = exactly
// one resident wave (<= 148 SMs x 4 CTAs) -> all blocks co-resident, so the
// per-batch spin-wait cannot deadlock.
// Phase 1: pool partial for (b, sp) with __ldcs streaming loads.
// Phase 2: spin until all 16 blocks of batch b posted partials, then each
//          block computes GEMV1 for its own 128-column K-slice (overlapped
//          with other batches' pool phase -> W1 DRAM latency is hidden).
// Phase 3: last finishing block of batch b runs LN + GELU + GEMV2 + top-8.
// All reduction orders are fixed -> deterministic output.
// ---------------------------------------------------------------------------
__global__ void __launch_bounds__(NTHR) fused_router(
    const float* __restrict__ x,
    const float* __restrict__ W1, const float* __restrict__ b1,
    const float* __restrict__ ln_g, const float* __restrict__ ln_b,
    const float* __restrict__ W2, const float* __restrict__ b2,
    float* __restrict__ out)
{
    __shared__ float sh_fold[4][KCHUNK];
    __shared__ float sh_pool[KCHUNK];
    __shared__ float sh_gacc[2][ROUTE_H];
    __shared__ unsigned int s_flag;

    int blk = blockIdx.x;
    int b   = blk / NSPLIT;
    int sp  = blk % NSPLIT;
    int t   = threadIdx.x;           // 0..511

    // ---------------- Phase 1: partial mean-pool ----------------
    {
        const float4* base = (const float4*)(x) +
            ((size_t)b * SEQ + (size_t)sp * SCHUNK) * (size_t)H4 + t;
        float4 acc = make_float4(0.f, 0.f, 0.f, 0.f);
#pragma unroll 8
        for (int s = 0; s < SCHUNK; s++) {
            float4 v = __ldcs(&base[(size_t)s * H4]);
            acc.x += v.x; acc.y += v.y; acc.z += v.z; acc.w += v.w;
        }
        float4* o = (float4*)(g_partial + ((size_t)sp * BATCH + b) * HIDDEN);
        o[t] = acc;
    }

    // ---------------- arrive + spin until batch b pooled ----------------
    __threadfence();                       // publish partials
    __syncthreads();
    if (t == 0) {
        atomicAdd(&g_cnt1[b], 1u);
        while (((volatile unsigned int*)g_cnt1)[b] < NSPLIT) { }
    }
    __syncthreads();
    __threadfence();                       // acquire all 16 partial slices

    // ---------------- Phase 2: GEMV1 K-slice for cols [sp*128, +128) -------
    int i0 = sp * KCHUNK;

    // Fold 16 partials for 128 columns: thread (col = t&127, part = t>>7)
    // folds 4 partials each; combine below. (L2-resident: just written.)
    {
        int col  = t & (KCHUNK - 1);
        int part = t >> 7;                 // 0..3
        float s = 0.f;
#pragma unroll
        for (int q = 0; q < NSPLIT / 4; q++) {
            int spp = part * (NSPLIT / 4) + q;
            s += g_partial[((size_t)spp * BATCH + b) * HIDDEN + i0 + col];
        }
        sh_fold[part][col] = s;
    }
    __syncthreads();
    if (t < KCHUNK) {
        sh_pool[t] = ((sh_fold[0][t] + sh_fold[1][t]) +
                      (sh_fold[2][t] + sh_fold[3][t])) * (1.0f / SEQ);
    }
    __syncthreads();

    // GEMV slice: 512 threads = 256 outputs x 2 row-halves of 64 rows.
    // 8 independent accumulators; W1 reads coalesced across j.
    {
        int j    = t & (ROUTE_H - 1);
        int half = t >> 8;                 // 0 or 1
        int r0   = i0 + half * 64;
        float a0 = 0.f, a1 = 0.f, a2 = 0.f, a3 = 0.f;
        float a4 = 0.f, a5 = 0.f, a6 = 0.f, a7 = 0.f;
#pragma unroll
        for (int r = 0; r < 64; r += 8) {
            const float* w = W1 + (size_t)(r0 + r) * ROUTE_H + j;
            int p = half * 64 + r;
            a0 += sh_pool[p + 0] * w[0 * ROUTE_H];
            a1 += sh_pool[p + 1] * w[1 * ROUTE_H];
            a2 += sh_pool[p + 2] * w[2 * ROUTE_H];
            a3 += sh_pool[p + 3] * w[3 * ROUTE_H];
            a4 += sh_pool[p + 4] * w[4 * ROUTE_H];
            a5 += sh_pool[p + 5] * w[5 * ROUTE_H];
            a6 += sh_pool[p + 6] * w[6 * ROUTE_H];
            a7 += sh_pool[p + 7] * w[7 * ROUTE_H];
        }
        sh_gacc[half][j] = ((a0 + a1) + (a2 + a3)) + ((a4 + a5) + (a6 + a7));
    }
    __syncthreads();
    if (t < ROUTE_H)
        g_hpart[((size_t)sp * BATCH + b) * ROUTE_H + t] =
            sh_gacc[0][t] + sh_gacc[1][t];

    // ---------------- election: last GEMV block runs the finale ------------
    __threadfence();                       // publish h-partial slice
    __syncthreads();
    if (t == 0) {
        unsigned int old = atomicAdd(&g_cnt2[b], 1u);
        s_flag = (old == NSPLIT - 1) ? 1u : 0u;
    }
    __syncthreads();
    if (!s_flag) return;
    __threadfence();                       // acquire all 16 h-slices

    // ---------------- Phase 3: finale (first 256 threads) ------------------
    __shared__ float sh_h[ROUTE_H];
    __shared__ float sh_w1r[8], sh_w2r[8];
    __shared__ float sh_part[ROUTE_H];
    __shared__ float sh_logits[NUM_EXPERTS];

    if (t < ROUTE_H) {
        int j    = t;
        int lane = t & 31;
        int warp = t >> 5;

        float h = 0.f;
#pragma unroll
        for (int k = 0; k < NSPLIT; k++)
            h += g_hpart[((size_t)k * BATCH + b) * ROUTE_H + j];
        h += b1[j];

        // LN reduce via warp shuffles (8 warps)
        float s1 = h, s2 = h * h;
#pragma unroll
        for (int o = 16; o > 0; o >>= 1) {
            s1 += __shfl_xor_sync(0xffffffffu, s1, o);
            s2 += __shfl_xor_sync(0xffffffffu, s2, o);
        }
        if (lane == 0) { sh_w1r[warp] = s1; sh_w2r[warp] = s2; }
        __syncwarp();
        // cross-warp combine via bar 1 scoped to 256 threads
        asm volatile("bar.sync 1, 256;" ::: "memory");
        float t1 = sh_w1r[lane & 7], t2 = sh_w2r[lane & 7];
#pragma unroll
        for (int o = 4; o > 0; o >>= 1) {
            t1 += __shfl_xor_sync(0xffffffffu, t1, o);
            t2 += __shfl_xor_sync(0xffffffffu, t2, o);
        }
        t1 = __shfl_sync(0xffffffffu, t1, 0);
        t2 = __shfl_sync(0xffffffffu, t2, 0);

        float mu  = t1 * (1.0f / ROUTE_H);
        float ms  = t2 * (1.0f / ROUTE_H);
        float inv = rsqrtf(ms - mu * mu + LN_EPS);
        h = (h - mu) * inv * ln_g[j] + ln_b[j];
        h = 0.5f * h * (1.0f + erff(h * 0.70710678118654752f)); // exact GELU
        sh_h[j] = h;
        asm volatile("bar.sync 1, 256;" ::: "memory");

        // GEMV2, K-split 4: 256 threads = 64 experts x 4 slices
        {
            int e   = j & (NUM_EXPERTS - 1);
            int ks2 = j >> 6;
            int r0  = ks2 * (ROUTE_H / 4);
            float a = 0.f;
#pragma unroll 8
            for (int i = 0; i < ROUTE_H / 4; i++)
                a += sh_h[r0 + i] * W2[(size_t)(r0 + i) * NUM_EXPERTS + e];
            sh_part[j] = a;
        }
        asm volatile("bar.sync 1, 256;" ::: "memory");
        if (j < NUM_EXPERTS) {
            sh_logits[j] = ((sh_part[j] + sh_part[j + 64]) +
                            (sh_part[j + 128] + sh_part[j + 192])) + b2[j];
            out[(size_t)b * NUM_EXPERTS + j] = 0.0f;  // d_out poisoned
        }
        asm volatile("bar.sync 1, 256;" ::: "memory");

        // top-8 + softmax + scatter (strict '>' = first-index tie-break,
        // matching jax.lax.top_k). Also reset counters for next graph replay.
        if (j == 0) {
            int   idx[TOP_K];
            float val[TOP_K];
            unsigned long long used = 0ull;
            for (int k = 0; k < TOP_K; k++) {
                float best = -INFINITY;
                int bi = 0;
                for (int e = 0; e < NUM_EXPERTS; e++) {
                    if (!((used >> e) & 1ull) && sh_logits[e] > best) {
                        best = sh_logits[e]; bi = e;
                    }
                }
                used |= (1ull << bi);
                idx[k] = bi;
                val[k] = best;
            }
            float mx = val[0];
            float denom = 0.f;
            float ex[TOP_K];
            for (int k = 0; k < TOP_K; k++) { ex[k] = expf(val[k] - mx); denom += ex[k]; }
            float rden = 1.0f / denom;
            for (int k = 0; k < TOP_K; k++)
                out[(size_t)b * NUM_EXPERTS + idx[k]] = ex[k] * rden;

            g_cnt1[b] = 0u;   // reset for next replay (this launch is done
            g_cnt2[b] = 0u;   // with them; resets are pre-kernel-end)
        }
    }
}

// ---------------------------------------------------------------------------
extern "C" void kernel_launch(void* const* d_in, const int* in_sizes, int n_in,
                              void* d_out, int out_size) {
    const float* hs   = (const float*)d_in[0];
    const float* W1   = (const float*)d_in[1];
    const float* b1   = (const float*)d_in[2];
    const float* ln_g = (const float*)d_in[3];
    const float* ln_b = (const float*)d_in[4];
    const float* W2   = (const float*)d_in[5];
    const float* b2   = (const float*)d_in[6];
    // d_in[7] = top_k (hardcoded 8)

    float* out = (float*)d_out;

    fused_router<<<BATCH * NSPLIT, NTHR>>>(hs, W1, b1, ln_g, ln_b, W2, b2, out);
}